// round 16
// baseline (speedup 1.0000x reference)
#include <cuda_runtime.h>
#include <cuda_fp16.h>
#include <cstdint>

#define IN_DIM   32768
#define CLASSES  100
#define BATCH    4096
#define NPAD     104                    // 13 n8-tiles
#define NTILES   13
#define KSTAGE   64
#define UNITS_PER_MTILE 512             // IN_DIM / KSTAGE
#define NMTILES  32
#define TOTAL_UNITS (NMTILES * UNITS_PER_MTILE)   // 16384
#define GRID     296                    // 148 SMs x occ 2, exact
#define ABYTES   (128 * 128)            // 16384
#define BBYTES   (NPAD * 128)           // 13312
#define STAGE_BYTES (ABYTES + BBYTES)   // 29696
#define THREADS  256

#define SWZ(o) ((o) ^ (((o) >> 3) & 0x70))

// ustart(c) = c * TOTAL_UNITS / GRID = c*2048/37 (exact integer form)
#define USTART(c) ((uint32_t)(((uint32_t)(c) * 2048u) / 37u))

__device__ __half g_signW[(size_t)NPAD * IN_DIM];                 // 6.8 MB
__device__ float  g_part[(size_t)GRID * 2 * 128 * NPAD];          // 31.5 MB per-CTA slots

// ---------------------------------------------------------------- helpers
__device__ __forceinline__ uint32_t smem_u32(const void* p) {
    uint32_t a;
    asm("{ .reg .u64 t; cvta.to.shared.u64 t, %1; cvt.u32.u64 %0, t; }" : "=r"(a) : "l"(p));
    return a;
}
__device__ __forceinline__ void ldsm_x4(uint32_t& r0, uint32_t& r1, uint32_t& r2, uint32_t& r3,
                                        uint32_t addr) {
    asm volatile("ldmatrix.sync.aligned.m8n8.x4.shared.b16 {%0,%1,%2,%3}, [%4];"
                 : "=r"(r0), "=r"(r1), "=r"(r2), "=r"(r3) : "r"(addr));
}
__device__ __forceinline__ void ldsm_x2(uint32_t& r0, uint32_t& r1, uint32_t addr) {
    asm volatile("ldmatrix.sync.aligned.m8n8.x2.shared.b16 {%0,%1}, [%2];"
                 : "=r"(r0), "=r"(r1) : "r"(addr));
}
__device__ __forceinline__ void mma16816(float* c, uint32_t a0, uint32_t a1, uint32_t a2,
                                         uint32_t a3, uint32_t b0, uint32_t b1) {
    asm volatile(
        "mma.sync.aligned.m16n8k16.row.col.f32.f16.f16.f32 "
        "{%0,%1,%2,%3}, {%4,%5,%6,%7}, {%8,%9}, {%0,%1,%2,%3};"
        : "+f"(c[0]), "+f"(c[1]), "+f"(c[2]), "+f"(c[3])
        : "r"(a0), "r"(a1), "r"(a2), "r"(a3), "r"(b0), "r"(b1));
}
__device__ __forceinline__ void sts128(uint32_t addr, uint32_t u0, uint32_t u1,
                                       uint32_t u2, uint32_t u3) {
    asm volatile("st.shared.v4.b32 [%0], {%1,%2,%3,%4};"
                 :: "r"(addr), "r"(u0), "r"(u1), "r"(u2), "r"(u3) : "memory");
}
__device__ __forceinline__ void cpasync16(uint32_t saddr, const void* gptr) {
    asm volatile("cp.async.cg.shared.global [%0], [%1], 16;"
                 :: "r"(saddr), "l"(gptr) : "memory");
}
__device__ __forceinline__ uint32_t packh2(float lo, float hi) {
    __half2 h = __floats2half2_rn(lo, hi);
    return *reinterpret_cast<uint32_t*>(&h);
}

// ---------------------------------------------------------------- kernel 1: sign(W) -> fp16
__global__ void sign_kernel(const float* __restrict__ W) {
    int i = blockIdx.x * 256 + threadIdx.x;      // granule = 8 elems; 104*4096 granules
    int n  = i >> 12;
    int k8 = i & 4095;
    __half2 h[4];
    if (n < CLASSES) {
        const float4* p = reinterpret_cast<const float4*>(W + ((size_t)n << 15)) + k8 * 2;
        float4 f0 = p[0], f1 = p[1];
        #define SG(v) ((v) > 0.f ? 1.f : ((v) < 0.f ? -1.f : 0.f))
        h[0] = __floats2half2_rn(SG(f0.x), SG(f0.y));
        h[1] = __floats2half2_rn(SG(f0.z), SG(f0.w));
        h[2] = __floats2half2_rn(SG(f1.x), SG(f1.y));
        h[3] = __floats2half2_rn(SG(f1.z), SG(f1.w));
        #undef SG
    } else {
        h[0] = h[1] = h[2] = h[3] = __floats2half2_rn(0.f, 0.f);
    }
    *reinterpret_cast<float4*>(g_signW + (size_t)i * 8) = *reinterpret_cast<float4*>(h);
}

// ---------------------------------------------------------------- kernel 2: balanced fp16 GEMM
__global__ __launch_bounds__(THREADS, 2)
void binmm_kernel(const float* __restrict__ x) {
    extern __shared__ char smraw[];
    uint32_t sb = (smem_u32(smraw) + 1023u) & ~1023u;

    const int tid  = threadIdx.x;
    const int lane = tid & 31;
    const int w    = tid >> 5;                    // 8 warps, each m16 x n104
    const int cta  = blockIdx.x;

    const uint32_t ustart = USTART(cta);
    const uint32_t uend   = USTART(cta + 1);

    // ---- producer geometry: per-thread row/col offsets (unit-relative) ----
    uint32_t aRowOff[4];                          // element offset of A granule within mtile
    uint32_t sAoff[4];
    uint32_t bRowOff[4];
    bool bAct[4];
    #pragma unroll
    for (int j = 0; j < 4; j++) {
        int g = tid + THREADS * j;                // 0..1023
        int row = g >> 3, c16 = g & 7;
        aRowOff[j] = (uint32_t)row * IN_DIM + c16 * 8;
        sAoff[j]   = SWZ((uint32_t)(row * 128 + c16 * 16));
        bAct[j]    = g < (NPAD * 8);              // 832 B-granules
        bRowOff[j] = aRowOff[j];
    }

    // ---- ldmatrix base offsets ----
    const int lm = lane >> 3, lr = lane & 7;
    const uint32_t aOff = SWZ((uint32_t)((16 * w + ((lm & 1) ? 8 : 0) + lr) * 128
                                         + (lm >> 1) * 16));
    const uint32_t bOff = SWZ((uint32_t)((((lm & 1) ? 8 : 0) + lr) * 128 + (lm >> 1) * 16));
    const uint32_t bX2  = SWZ((uint32_t)((96 + (lane & 7)) * 128 + ((lane >> 3) & 1) * 16));

    float acc[NTILES][4];
    #pragma unroll
    for (int t = 0; t < NTILES; t++)
        #pragma unroll
        for (int q = 0; q < 4; q++) acc[t][q] = 0.f;

    float4 fa[4];

    #define ABASE(u) (x + (((size_t)((u) >> 9)) << 22) + (size_t)(((u) & 511u) << 6))
    #define BBASE(u) (g_signW + (size_t)(((u) & 511u) << 6))

    #define LOADA2(u, h) do {                                                     \
        const float* _b = ABASE(u);                                               \
        _Pragma("unroll")                                                         \
        for (int j = 0; j < 2; j++) {                                             \
            const float* _p = _b + aRowOff[2 * (h) + j];                          \
            fa[j * 2]     = *reinterpret_cast<const float4*>(_p);                 \
            fa[j * 2 + 1] = *reinterpret_cast<const float4*>(_p + 4);             \
        }                                                                         \
    } while (0)

    #define STSA2(soff, h) do {                                                   \
        _Pragma("unroll")                                                         \
        for (int j = 0; j < 2; j++) {                                             \
            float4 f0 = fa[j * 2], f1 = fa[j * 2 + 1];                            \
            sts128(sb + (soff) + sAoff[2 * (h) + j],                              \
                   packh2(f0.x, f0.y), packh2(f0.z, f0.w),                        \
                   packh2(f1.x, f1.y), packh2(f1.z, f1.w));                       \
        }                                                                         \
    } while (0)

    #define CPB(u, soff) do {                                                     \
        const __half* _b = BBASE(u);                                              \
        _Pragma("unroll")                                                         \
        for (int j = 0; j < 4; j++)                                               \
            if (bAct[j])                                                          \
                cpasync16(sb + (soff) + ABYTES + sAoff[j], _b + bRowOff[j]);      \
    } while (0)

    #define COMPUTE(soff) do {                                                    \
        const uint32_t aA = sb + (soff) + aOff;                                   \
        const uint32_t bA = sb + (soff) + ABYTES + bOff;                          \
        const uint32_t bX = sb + (soff) + ABYTES + bX2;                           \
        _Pragma("unroll")                                                         \
        for (int t = 0; t < 4; t++) {                                             \
            const uint32_t kx = 32u * t;                                          \
            uint32_t a0, a1, a2, a3;                                              \
            ldsm_x4(a0, a1, a2, a3, aA ^ kx);                                     \
            _Pragma("unroll")                                                     \
            for (int p = 0; p < 6; p++) {                                         \
                uint32_t b0, b1, b2, b3;                                          \
                ldsm_x4(b0, b1, b2, b3, (bA + p * 2048) ^ kx);                    \
                mma16816(acc[2 * p],     a0, a1, a2, a3, b0, b2);                 \
                mma16816(acc[2 * p + 1], a0, a1, a2, a3, b1, b3);                 \
            }                                                                     \
            uint32_t c0, c1;                                                      \
            ldsm_x2(c0, c1, bX ^ kx);                                             \
            mma16816(acc[12], a0, a1, a2, a3, c0, c1);                            \
        }                                                                         \
    } while (0)

    const int r0 = 16 * w + (lane >> 2);
    #define FLUSH(which) do {                                                     \
        size_t _base = ((size_t)(cta * 2 + (which)) * 128 + r0) * NPAD;           \
        _Pragma("unroll")                                                         \
        for (int nt = 0; nt < NTILES; nt++) {                                     \
            int n = nt * 8 + (lane & 3) * 2;                                      \
            *reinterpret_cast<float2*>(&g_part[_base + n]) =                      \
                make_float2(acc[nt][0], acc[nt][1]);                              \
            *reinterpret_cast<float2*>(&g_part[_base + 8 * NPAD + n]) =           \
                make_float2(acc[nt][2], acc[nt][3]);                              \
            acc[nt][0] = acc[nt][1] = acc[nt][2] = acc[nt][3] = 0.f;              \
        }                                                                         \
    } while (0)

    // ---- prologue: units ustart, ustart+1 into stages 0,1 ----
    LOADA2(ustart, 0); STSA2(0, 0); LOADA2(ustart, 1); STSA2(0, 1); CPB(ustart, 0);
    asm volatile("cp.async.commit_group;" ::: "memory");
    LOADA2(ustart + 1, 0); STSA2(STAGE_BYTES, 0);
    LOADA2(ustart + 1, 1); STSA2(STAGE_BYTES, 1);
    CPB(ustart + 1, STAGE_BYTES);
    asm volatile("cp.async.commit_group;" ::: "memory");

    // ---- mainloop over units ----
    uint32_t curt = ustart >> 9;
    int nflush = 0;
    int s = 0;
    for (uint32_t u = ustart; u < uend; u++) {
        asm volatile("cp.async.wait_group 1;" ::: "memory");
        __syncthreads();

        if ((u >> 9) != curt) {                   // mtile boundary: flush partials
            FLUSH(nflush);
            nflush = 1;
            curt = u >> 9;
        }

        const bool pf = (u + 2) < uend;
        int s2 = s + 2; if (s2 >= 3) s2 -= 3;
        const uint32_t soff  = (uint32_t)s * STAGE_BYTES;
        const uint32_t soff2 = (uint32_t)s2 * STAGE_BYTES;

        if (pf) {
            LOADA2(u + 2, 0);
            CPB(u + 2, soff2);
        }
        asm volatile("cp.async.commit_group;" ::: "memory");

        COMPUTE(soff);

        if (pf) {
            STSA2(soff2, 0);
            LOADA2(u + 2, 1);
            STSA2(soff2, 1);
        }
        if (++s == 3) s = 0;
    }

    FLUSH(nflush);                                // final flush

    #undef ABASE
    #undef BBASE
    #undef LOADA2
    #undef STSA2
    #undef CPB
    #undef COMPUTE
    #undef FLUSH
}

// ---------------------------------------------------------------- kernel 3: finalize
__global__ void finalize_kernel(float* __restrict__ out) {
    int idx = blockIdx.x * 256 + threadIdx.x;     // 4096*100 = 1600 blocks
    int m = idx / CLASSES;
    int n = idx - m * CLASSES;
    const uint32_t t = (uint32_t)(m >> 7);        // mtile
    const float scale = 0.0055242717280199026f;   // 1/sqrt(32768)

    float a = 0.f;
    int c0 = (int)((t * 37u) >> 2) - 1;           // ~ floor(9.25 t) - 1
    if (c0 < 0) c0 = 0;
    for (int c = c0; c < GRID; c++) {
        uint32_t us = USTART(c);
        if (us >= (t + 1) * UNITS_PER_MTILE) break;
        uint32_t ue = USTART(c + 1);
        if (ue <= t * UNITS_PER_MTILE) continue;
        int which = ((us >> 9) == t) ? 0 : 1;
        a += g_part[((size_t)(c * 2 + which) * 128 + (m & 127)) * NPAD + n];
    }
    out[idx] = a * scale;
}

// ---------------------------------------------------------------- launch
extern "C" void kernel_launch(void* const* d_in, const int* in_sizes, int n_in,
                              void* d_out, int out_size) {
    const float* x = (const float*)d_in[0];
    const float* W = (const float*)d_in[1];
    float* out = (float*)d_out;

    const int SMEM_DYN = 3 * STAGE_BYTES + 1024;  // ~90 KB, 2 CTAs/SM fit in 227 KB
    cudaFuncSetAttribute(binmm_kernel, cudaFuncAttributeMaxDynamicSharedMemorySize, SMEM_DYN);

    sign_kernel<<<(NPAD * IN_DIM / 8) / 256, 256>>>(W);
    binmm_kernel<<<GRID, THREADS, SMEM_DYN>>>(x);
    finalize_kernel<<<(BATCH * CLASSES) / 256, 256>>>(out);
}

// round 17
// speedup vs baseline: 1.6569x; 1.6569x over previous
#include <cuda_runtime.h>
#include <cuda_fp16.h>
#include <cstdint>

#define IN_DIM   32768
#define CLASSES  100
#define BATCH    4096
#define NPAD     104                    // 13 n8-tiles
#define NTILES   13
#define SPLITS   8
#define KSPLIT   (IN_DIM / SPLITS)       // 4096
#define KSTAGE   64
#define NITER    (KSPLIT / KSTAGE)       // 64
#define ABYTES   (128 * 128)             // 16384
#define BBYTES   (NPAD * 128)            // 13312
#define STAGE_BYTES (ABYTES + BBYTES)    // 29696
#define THREADS  256

#define SWZ(o) ((o) ^ (((o) >> 3) & 0x70))

__device__ __half g_signW[(size_t)NPAD * IN_DIM];            // 6.8 MB fp16 sign(W), padded
__device__ float  g_partial[(size_t)SPLITS * BATCH * NPAD];  // 13.6 MB split-K partials

// ---------------------------------------------------------------- helpers
__device__ __forceinline__ uint32_t smem_u32(const void* p) {
    uint32_t a;
    asm("{ .reg .u64 t; cvta.to.shared.u64 t, %1; cvt.u32.u64 %0, t; }" : "=r"(a) : "l"(p));
    return a;
}
__device__ __forceinline__ void ldsm_x4(uint32_t& r0, uint32_t& r1, uint32_t& r2, uint32_t& r3,
                                        uint32_t addr) {
    asm volatile("ldmatrix.sync.aligned.m8n8.x4.shared.b16 {%0,%1,%2,%3}, [%4];"
                 : "=r"(r0), "=r"(r1), "=r"(r2), "=r"(r3) : "r"(addr));
}
__device__ __forceinline__ void ldsm_x2(uint32_t& r0, uint32_t& r1, uint32_t addr) {
    asm volatile("ldmatrix.sync.aligned.m8n8.x2.shared.b16 {%0,%1}, [%2];"
                 : "=r"(r0), "=r"(r1) : "r"(addr));
}
__device__ __forceinline__ void mma16816(float* c, uint32_t a0, uint32_t a1, uint32_t a2,
                                         uint32_t a3, uint32_t b0, uint32_t b1) {
    asm volatile(
        "mma.sync.aligned.m16n8k16.row.col.f32.f16.f16.f32 "
        "{%0,%1,%2,%3}, {%4,%5,%6,%7}, {%8,%9}, {%0,%1,%2,%3};"
        : "+f"(c[0]), "+f"(c[1]), "+f"(c[2]), "+f"(c[3])
        : "r"(a0), "r"(a1), "r"(a2), "r"(a3), "r"(b0), "r"(b1));
}
__device__ __forceinline__ void sts128(uint32_t addr, uint32_t u0, uint32_t u1,
                                       uint32_t u2, uint32_t u3) {
    asm volatile("st.shared.v4.b32 [%0], {%1,%2,%3,%4};"
                 :: "r"(addr), "r"(u0), "r"(u1), "r"(u2), "r"(u3) : "memory");
}
__device__ __forceinline__ void cpasync16(uint32_t saddr, const void* gptr) {
    asm volatile("cp.async.cg.shared.global [%0], [%1], 16;"
                 :: "r"(saddr), "l"(gptr) : "memory");
}
__device__ __forceinline__ uint32_t packh2(float lo, float hi) {
    __half2 h = __floats2half2_rn(lo, hi);
    return *reinterpret_cast<uint32_t*>(&h);
}

// ---------------------------------------------------------------- kernel 1: sign(W) -> fp16
__global__ void sign_kernel(const float* __restrict__ W) {
    int i = blockIdx.x * 256 + threadIdx.x;      // granule = 8 elements; NPAD*4096 granules
    int n  = i >> 12;
    int k8 = i & 4095;
    __half2 h[4];
    if (n < CLASSES) {
        const float4* p = reinterpret_cast<const float4*>(W + ((size_t)n << 15)) + k8 * 2;
        float4 f0 = p[0], f1 = p[1];
        #define SG(v) ((v) > 0.f ? 1.f : ((v) < 0.f ? -1.f : 0.f))
        h[0] = __floats2half2_rn(SG(f0.x), SG(f0.y));
        h[1] = __floats2half2_rn(SG(f0.z), SG(f0.w));
        h[2] = __floats2half2_rn(SG(f1.x), SG(f1.y));
        h[3] = __floats2half2_rn(SG(f1.z), SG(f1.w));
        #undef SG
    } else {
        h[0] = h[1] = h[2] = h[3] = __floats2half2_rn(0.f, 0.f);
    }
    *reinterpret_cast<float4*>(g_signW + (size_t)i * 8) = *reinterpret_cast<float4*>(h);
}

// ---------------------------------------------------------------- kernel 2: split-K fp16 GEMM
__global__ __launch_bounds__(THREADS, 2)
void binmm_kernel(const float* __restrict__ x) {
    extern __shared__ char smraw[];
    uint32_t sb = (smem_u32(smraw) + 1023u) & ~1023u;

    const int tid  = threadIdx.x;
    const int lane = tid & 31;
    const int w    = tid >> 5;
    const int bid  = blockIdx.x;
    const int mtile = bid & 31;
    const int split = bid >> 5;                  // 0..7
    const size_t m0 = (size_t)mtile * 128;
    const int kbase = split * KSPLIT;

    // ---- producer geometry (per thread) ----
    const float* pA[4];
    uint32_t sA[4];
    const __half* pB[4];
    bool bAct[4];
    #pragma unroll
    for (int j = 0; j < 4; j++) {
        int g = tid + THREADS * j;               // A: 1024 granules of 16B smem (8 halves)
        int row = g >> 3, c16 = g & 7;
        pA[j] = x + (m0 + (size_t)row) * IN_DIM + kbase + c16 * 8;
        sA[j] = SWZ((uint32_t)(row * 128 + c16 * 16));
        bAct[j] = g < (NPAD * 8);                // B: 832 granules
        pB[j] = g_signW + (size_t)row * IN_DIM + kbase + c16 * 8;
    }

    // ---- ldmatrix base addresses ----
    const int lm = lane >> 3, lr = lane & 7;
    const int arow = 16 * w + ((lm & 1) ? 8 : 0) + lr;
    const uint32_t aOff = SWZ((uint32_t)(arow * 128 + (lm >> 1) * 16));
    const int brow = ((lm & 1) ? 8 : 0) + lr;
    const uint32_t bOff = SWZ((uint32_t)(brow * 128 + (lm >> 1) * 16));
    const uint32_t bX2  = SWZ((uint32_t)((96 + (lane & 7)) * 128 + ((lane >> 3) & 1) * 16));

    float acc[NTILES][4];
    #pragma unroll
    for (int t = 0; t < NTILES; t++)
        #pragma unroll
        for (int q = 0; q < 4; q++) acc[t][q] = 0.f;

    float4 fa[4];   // HALF of an A-stage in flight (16 regs) to stay under the occ-2 budget

    #define LOADA2(it, h) do {                                                    \
        _Pragma("unroll")                                                         \
        for (int j = 0; j < 2; j++) {                                             \
            const float* _p = pA[2 * (h) + j] + (size_t)(it) * KSTAGE;            \
            fa[j * 2]     = *reinterpret_cast<const float4*>(_p);                 \
            fa[j * 2 + 1] = *reinterpret_cast<const float4*>(_p + 4);             \
        }                                                                         \
    } while (0)

    #define STSA2(soff, h) do {                                                   \
        _Pragma("unroll")                                                         \
        for (int j = 0; j < 2; j++) {                                             \
            float4 f0 = fa[j * 2], f1 = fa[j * 2 + 1];                            \
            sts128(sb + (soff) + sA[2 * (h) + j],                                 \
                   packh2(f0.x, f0.y), packh2(f0.z, f0.w),                        \
                   packh2(f1.x, f1.y), packh2(f1.z, f1.w));                       \
        }                                                                         \
    } while (0)

    #define CPB(it, soff) do {                                                    \
        _Pragma("unroll")                                                         \
        for (int j = 0; j < 4; j++)                                               \
            if (bAct[j])                                                          \
                cpasync16(sb + (soff) + ABYTES + sA[j], pB[j] + (size_t)(it) * KSTAGE); \
    } while (0)

    #define COMPUTE_HALF(aA, bA, bXa, tlo) do {                                   \
        _Pragma("unroll")                                                         \
        for (int t = (tlo); t < (tlo) + 2; t++) {                                 \
            const uint32_t kx = 32u * t;                                          \
            uint32_t a0, a1, a2, a3;                                              \
            ldsm_x4(a0, a1, a2, a3, (aA) ^ kx);                                   \
            _Pragma("unroll")                                                     \
            for (int p = 0; p < 6; p++) {                                         \
                uint32_t b0, b1, b2, b3;                                          \
                ldsm_x4(b0, b1, b2, b3, ((bA) + p * 2048) ^ kx);                  \
                mma16816(acc[2 * p],     a0, a1, a2, a3, b0, b2);                 \
                mma16816(acc[2 * p + 1], a0, a1, a2, a3, b1, b3);                 \
            }                                                                     \
            uint32_t c0, c1;                                                      \
            ldsm_x2(c0, c1, (bXa) ^ kx);                                          \
            mma16816(acc[12], a0, a1, a2, a3, c0, c1);                            \
        }                                                                         \
    } while (0)

    // ---- prologue: stages 0 and 1 ----
    LOADA2(0, 0); STSA2(0, 0); LOADA2(0, 1); STSA2(0, 1); CPB(0, 0);
    asm volatile("cp.async.commit_group;" ::: "memory");
    LOADA2(1, 0); STSA2(STAGE_BYTES, 0); LOADA2(1, 1); STSA2(STAGE_BYTES, 1);
    CPB(1, STAGE_BYTES);
    asm volatile("cp.async.commit_group;" ::: "memory");

    // ---- mainloop ----
    int s = 0;
    for (int i = 0; i < NITER; i++) {
        asm volatile("cp.async.wait_group 1;" ::: "memory");
        __syncthreads();

        const bool pf = (i + 2) < NITER;
        int s2 = s + 2; if (s2 >= 3) s2 -= 3;
        const uint32_t soff  = (uint32_t)s * STAGE_BYTES;
        const uint32_t soff2 = (uint32_t)s2 * STAGE_BYTES;

        if (pf) {
            LOADA2(i + 2, 0);
            CPB(i + 2, soff2);
        }
        asm volatile("cp.async.commit_group;" ::: "memory");

        const uint32_t aA = sb + soff + aOff;
        const uint32_t bA = sb + soff + ABYTES + bOff;
        const uint32_t bX = sb + soff + ABYTES + bX2;

        COMPUTE_HALF(aA, bA, bX, 0);
        if (pf) { STSA2(soff2, 0); LOADA2(i + 2, 1); }
        COMPUTE_HALF(aA, bA, bX, 2);
        if (pf) STSA2(soff2, 1);

        if (++s == 3) s = 0;
    }

    // ---- epilogue: store split-K partials ----
    const int r0 = 16 * w + (lane >> 2);
    #pragma unroll
    for (int nt = 0; nt < NTILES; nt++) {
        int n = nt * 8 + (lane & 3) * 2;
        size_t idx = ((size_t)split * BATCH + m0 + r0) * NPAD + n;
        *reinterpret_cast<float2*>(&g_partial[idx]) = make_float2(acc[nt][0], acc[nt][1]);
        *reinterpret_cast<float2*>(&g_partial[idx + 8 * NPAD]) = make_float2(acc[nt][2], acc[nt][3]);
    }
    #undef LOADA2
    #undef STSA2
    #undef CPB
    #undef COMPUTE_HALF
}

// ---------------------------------------------------------------- kernel 3: split-K reduce
__global__ void reduce_kernel(float* __restrict__ out) {
    int idx = blockIdx.x * 256 + threadIdx.x;   // BATCH * CLASSES
    int m = idx / CLASSES;
    int n = idx - m * CLASSES;
    const float scale = 0.0055242717280199026f; // 1/sqrt(32768)
    float a = 0.f;
    #pragma unroll
    for (int s = 0; s < SPLITS; s++)
        a += g_partial[((size_t)s * BATCH + m) * NPAD + n];
    out[idx] = a * scale;
}

// ---------------------------------------------------------------- launch
extern "C" void kernel_launch(void* const* d_in, const int* in_sizes, int n_in,
                              void* d_out, int out_size) {
    const float* x = (const float*)d_in[0];
    const float* W = (const float*)d_in[1];
    float* out = (float*)d_out;

    const int SMEM_DYN = 3 * STAGE_BYTES + 1024;
    cudaFuncSetAttribute(binmm_kernel, cudaFuncAttributeMaxDynamicSharedMemorySize, SMEM_DYN);

    sign_kernel<<<(NPAD * IN_DIM / 8) / 256, 256>>>(W);
    binmm_kernel<<<SPLITS * 32, THREADS, SMEM_DYN>>>(x);
    reduce_kernel<<<(BATCH * CLASSES) / 256, 256>>>(out);
}